// round 15
// baseline (speedup 1.0000x reference)
#include <cuda_runtime.h>
#include <cstdint>

#define DIMV 512
#define KMAX 8192
#define NMAX 32768

#define BM 128
#define BK 128
#define BD2 16
#define TMARGIN 6.5e-4f

// ---------------- scratch (device globals; no allocation allowed) ----------
__device__ float  g_csq[KMAX];
__device__ float  g_xsq[NMAX];
__device__ int    g_idx[NMAX];
__device__ double g_part[NMAX / 8];

__device__ __align__(16) int g_x8[(size_t)NMAX * (DIMV / 4)];   // packed int8, d-major
__device__ __align__(16) int g_c8[(size_t)KMAX * (DIMV / 4)];
__device__ float g_sx[NMAX];      // per-token int8 scale
__device__ float g_sc2[KMAX];     // 2 * per-code int8 scale
__device__ int   g_ci[(size_t)NMAX * 4];
__device__ int   g_count;
__device__ int   g_list[NMAX];

// sorted-ascending top-4 insert
__device__ __forceinline__ void ins4(float v, int i, float* tv, int* ti) {
    if (v < tv[3]) {
        if (v < tv[2]) {
            tv[3] = tv[2]; ti[3] = ti[2];
            if (v < tv[1]) {
                tv[2] = tv[1]; ti[2] = ti[1];
                if (v < tv[0]) { tv[1] = tv[0]; ti[1] = ti[0]; tv[0] = v; ti[0] = i; }
                else           { tv[1] = v; ti[1] = i; }
            } else { tv[2] = v; ti[2] = i; }
        } else { tv[3] = v; ti[3] = i; }
    }
}

// ---------------------------------------------------------------------------
// Row sum-of-squares (EXACT pipeline, op order unchanged -> feeds rescore /
// fallback bit-identically) + per-row max-abs int8 pack.
// ---------------------------------------------------------------------------
__global__ void xsq_kernel(const float* __restrict__ x, int rows) {
    int warp = (blockIdx.x * blockDim.x + threadIdx.x) >> 5;
    int lane = threadIdx.x & 31;
    if (warp >= rows) return;
    const float* r = x + (size_t)warp * DIMV;
    float acc = 0.f;
    #pragma unroll 4
    for (int j = lane; j < DIMV; j += 32) {
        float v = r[j];
        acc = __fadd_rn(acc, __fmul_rn(v, v));
    }
    #pragma unroll
    for (int off = 16; off > 0; off >>= 1)
        acc = __fadd_rn(acc, __shfl_down_sync(0xffffffffu, acc, off));
    if (lane == 0) g_xsq[warp] = acc;

    // max-abs + int8 pack (separate pass; does not touch xsq op order)
    float mx = 0.f;
    for (int j = lane; j < DIMV; j += 32) mx = fmaxf(mx, fabsf(r[j]));
    #pragma unroll
    for (int off = 16; off > 0; off >>= 1)
        mx = fmaxf(mx, __shfl_xor_sync(0xffffffffu, mx, off));
    mx = fmaxf(mx, 1e-20f);
    float scale = mx / 127.f;
    float inv = 127.f / mx;
    if (lane == 0) g_sx[warp] = scale;
    const float4* r4 = (const float4*)r;
    int4 pk;
    int* pko = &pk.x;
    #pragma unroll
    for (int q = 0; q < 4; q++) {
        float4 v = r4[lane * 4 + q];
        int b0 = min(127, max(-127, (int)rintf(v.x * inv)));
        int b1 = min(127, max(-127, (int)rintf(v.y * inv)));
        int b2 = min(127, max(-127, (int)rintf(v.z * inv)));
        int b3 = min(127, max(-127, (int)rintf(v.w * inv)));
        pko[q] = (b0 & 0xFF) | ((b1 & 0xFF) << 8) | ((b2 & 0xFF) << 16) | (b3 << 24);
    }
    *(int4*)&g_x8[(size_t)warp * (DIMV / 4) + lane * 4] = pk;
}

__global__ void csq_kernel(const float* __restrict__ cb, int rows) {
    if (blockIdx.x == 0 && threadIdx.x == 0) g_count = 0;
    int warp = (blockIdx.x * blockDim.x + threadIdx.x) >> 5;
    int lane = threadIdx.x & 31;
    if (warp >= rows) return;
    const float* r = cb + (size_t)warp * DIMV;
    float acc = 0.f;
    #pragma unroll 4
    for (int j = lane; j < DIMV; j += 32) {
        float v = r[j];
        acc = __fadd_rn(acc, __fmul_rn(v, v));
    }
    #pragma unroll
    for (int off = 16; off > 0; off >>= 1)
        acc = __fadd_rn(acc, __shfl_down_sync(0xffffffffu, acc, off));
    if (lane == 0) g_csq[warp] = acc;

    float mx = 0.f;
    for (int j = lane; j < DIMV; j += 32) mx = fmaxf(mx, fabsf(r[j]));
    #pragma unroll
    for (int off = 16; off > 0; off >>= 1)
        mx = fmaxf(mx, __shfl_xor_sync(0xffffffffu, mx, off));
    mx = fmaxf(mx, 1e-20f);
    float scale = mx / 127.f;
    float inv = 127.f / mx;
    if (lane == 0) g_sc2[warp] = 2.f * scale;
    const float4* r4 = (const float4*)r;
    int4 pk;
    int* pko = &pk.x;
    #pragma unroll
    for (int q = 0; q < 4; q++) {
        float4 v = r4[lane * 4 + q];
        int b0 = min(127, max(-127, (int)rintf(v.x * inv)));
        int b1 = min(127, max(-127, (int)rintf(v.y * inv)));
        int b2 = min(127, max(-127, (int)rintf(v.z * inv)));
        int b3 = min(127, max(-127, (int)rintf(v.w * inv)));
        pko[q] = (b0 & 0xFF) | ((b1 & 0xFF) << 8) | ((b2 & 0xFF) << 16) | (b3 << 24);
    }
    *(int4*)&g_c8[(size_t)warp * (DIMV / 4) + lane * 4] = pk;
}

// ---------------------------------------------------------------------------
// Coarse candidate kernel: int8 dp4a argmin-GEMM.
// CTA = 128 tokens, 512 threads. ty=tid>>4 owns tokens ty*4..+3; tx=tid&15
// owns codes tx*8..+7 of each 128-code tile. Double-buffered 64-dim chunks
// (16 int32 dims), register prefetch, one __syncthreads per chunk (distance-2
// buffer argument as in the validated R14 pipeline).
// Coarse score: s̃ = csq - (float)idot * sx * (2*sc). Per-thread top-4 per
// token; half-warp shfl merge (the 16 tx-threads of a token group are lanes
// 0-15 / 16-31 of one warp). Token flagged if merged cv3-cv0 < TMARGIN.
// ---------------------------------------------------------------------------
__global__ __launch_bounds__(512, 1) void coarse_i8(int K) {
    __shared__ int xs8[2][BD2][BM];
    __shared__ int cs8[2][BD2][BK];

    const int tid = threadIdx.x;
    const int ty  = tid >> 4;        // 0..31
    const int tx  = tid & 15;        // 0..15
    const int m0  = blockIdx.x * BM;
    const int srow = tid & 127;      // staging row
    const int spq  = tid >> 7;       // 0..3 -> int32 quad within chunk

    float sxv[4];
    const int tok0 = m0 + ty * 4;
    #pragma unroll
    for (int i = 0; i < 4; i++) sxv[i] = g_sx[tok0 + i];

    float tv[4][4];
    int   ti[4][4];
    #pragma unroll
    for (int i = 0; i < 4; i++)
        #pragma unroll
        for (int q = 0; q < 4; q++) { tv[i][q] = 3.4e38f; ti[i][q] = 0; }

    const int ntiles  = K / BK;
    const int nchunks = ntiles * 8;

    int4 pfx = *(const int4*)&g_x8[(size_t)(m0 + srow) * (DIMV / 4) + spq * 4];
    int4 pfc = *(const int4*)&g_c8[(size_t)srow * (DIMV / 4) + spq * 4];

    for (int t = 0; t < ntiles; t++) {
        int acc[4][8];
        #pragma unroll
        for (int i = 0; i < 4; i++)
            #pragma unroll
            for (int j = 0; j < 8; j++) acc[i][j] = 0;

        for (int ch = 0; ch < 8; ch++) {
            const int c = t * 8 + ch;
            const int p = c & 1;
            // commit prefetched chunk (transpose to d-major)
            xs8[p][spq * 4 + 0][srow] = pfx.x;
            xs8[p][spq * 4 + 1][srow] = pfx.y;
            xs8[p][spq * 4 + 2][srow] = pfx.z;
            xs8[p][spq * 4 + 3][srow] = pfx.w;
            cs8[p][spq * 4 + 0][srow] = pfc.x;
            cs8[p][spq * 4 + 1][srow] = pfc.y;
            cs8[p][spq * 4 + 2][srow] = pfc.z;
            cs8[p][spq * 4 + 3][srow] = pfc.w;
            // prefetch next chunk
            int cn = c + 1;
            if (cn >= nchunks) cn = 0;
            const int tn = cn >> 3, chn = cn & 7;
            pfx = *(const int4*)&g_x8[(size_t)(m0 + srow) * (DIMV / 4) + chn * 16 + spq * 4];
            pfc = *(const int4*)&g_c8[(size_t)(tn * BK + srow) * (DIMV / 4) + chn * 16 + spq * 4];

            __syncthreads();

            #pragma unroll
            for (int dd = 0; dd < BD2; dd++) {
                int4 a  = *(const int4*)&xs8[p][dd][ty * 4];
                int4 b0 = *(const int4*)&cs8[p][dd][tx * 8];
                int4 b1 = *(const int4*)&cs8[p][dd][tx * 8 + 4];
                const int* ar = &a.x;
                const int* br0 = &b0.x;
                const int* br1 = &b1.x;
                #pragma unroll
                for (int i = 0; i < 4; i++) {
                    #pragma unroll
                    for (int j = 0; j < 4; j++) {
                        acc[i][j]     = __dp4a(ar[i], br0[j], acc[i][j]);
                        acc[i][j + 4] = __dp4a(ar[i], br1[j], acc[i][j + 4]);
                    }
                }
            }
        }

        // finalize this tile: thread's codes are contiguous tx*8..tx*8+7
        #pragma unroll
        for (int j = 0; j < 8; j++) {
            int code = t * BK + tx * 8 + j;
            float cq = __ldg(&g_csq[code]);
            float m2 = __ldg(&g_sc2[code]);
            #pragma unroll
            for (int i = 0; i < 4; i++) {
                float f = (float)acc[i][j];          // exact: |idot| < 2^24
                float s = __fmaf_rn(-f * sxv[i], m2, cq);
                ins4(s, code, tv[i], ti[i]);
            }
        }
        __syncthreads();   // all reads of buf done before next tile's commits
    }

    // merge the 16 tx-threads (one half-warp) per token group
    #pragma unroll
    for (int off = 1; off <= 8; off <<= 1) {
        #pragma unroll
        for (int i = 0; i < 4; i++) {
            float ov[4]; int oi[4];
            #pragma unroll
            for (int q = 0; q < 4; q++) {
                ov[q] = __shfl_xor_sync(0xffffffffu, tv[i][q], off);
                oi[q] = __shfl_xor_sync(0xffffffffu, ti[i][q], off);
            }
            #pragma unroll
            for (int q = 0; q < 4; q++) ins4(ov[q], oi[q], tv[i], ti[i]);
        }
    }

    if (tx == 0) {
        #pragma unroll
        for (int i = 0; i < 4; i++) {
            int tok = tok0 + i;
            #pragma unroll
            for (int q = 0; q < 4; q++) g_ci[4 * tok + q] = ti[i][q];
            if (tv[i][3] - tv[i][0] < TMARGIN) {
                int p = atomicAdd(&g_count, 1);
                g_list[p] = tok;
            }
        }
    }
}

// ---------------------------------------------------------------------------
// Exact rescore of the 4 candidates: bit-identical R4 pipeline.
// ---------------------------------------------------------------------------
__global__ void rescore_kernel(const float* __restrict__ x,
                               const float* __restrict__ cb, int n) {
    int gt = blockIdx.x * blockDim.x + threadIdx.x;
    int tok = gt >> 2, j = gt & 3;
    if (tok >= n) return;
    int code = g_ci[4 * tok + j];
    const float4* xr = (const float4*)(x + (size_t)tok * DIMV);
    const float4* cr = (const float4*)(cb + (size_t)code * DIMV);
    float acc = 0.f;
    #pragma unroll 8
    for (int q = 0; q < DIMV / 4; q++) {
        float4 a = __ldg(xr + q), c = __ldg(cr + q);
        acc = __fmaf_rn(a.x, c.x, acc);
        acc = __fmaf_rn(a.y, c.y, acc);
        acc = __fmaf_rn(a.z, c.z, acc);
        acc = __fmaf_rn(a.w, c.w, acc);
    }
    float v = __fadd_rn(__fmaf_rn(-2.f, acc, g_xsq[tok]), g_csq[code]);
    #pragma unroll
    for (int off = 1; off < 4; off <<= 1) {
        float ov = __shfl_xor_sync(0xffffffffu, v, off);
        int   oc = __shfl_xor_sync(0xffffffffu, code, off);
        if (ov < v || (ov == v && oc < code)) { v = ov; code = oc; }
    }
    if (j == 0) g_idx[tok] = code;
}

// ---------------------------------------------------------------------------
// Fallback: full exact scan for flagged tokens (few %).
// ---------------------------------------------------------------------------
__global__ void fallback_kernel(const float* __restrict__ x,
                                const float* __restrict__ cb, int K) {
    __shared__ float sv[256];
    __shared__ int   si[256];
    int nf = g_count;
    for (int li = blockIdx.x; li < nf; li += gridDim.x) {
        int tok = g_list[li];
        float xsq = g_xsq[tok];
        const float4* xr = (const float4*)(x + (size_t)tok * DIMV);
        float bv = 3.4e38f; int bi = 0x7fffffff;
        for (int code = threadIdx.x; code < K; code += 256) {
            const float4* cr = (const float4*)(cb + (size_t)code * DIMV);
            float acc = 0.f;
            #pragma unroll 8
            for (int q = 0; q < DIMV / 4; q++) {
                float4 a = xr[q], c = __ldg(cr + q);
                acc = __fmaf_rn(a.x, c.x, acc);
                acc = __fmaf_rn(a.y, c.y, acc);
                acc = __fmaf_rn(a.z, c.z, acc);
                acc = __fmaf_rn(a.w, c.w, acc);
            }
            float v = __fadd_rn(__fmaf_rn(-2.f, acc, xsq), g_csq[code]);
            if (v < bv || (v == bv && code < bi)) { bv = v; bi = code; }
        }
        sv[threadIdx.x] = bv; si[threadIdx.x] = bi;
        __syncthreads();
        for (int st = 128; st > 0; st >>= 1) {
            if (threadIdx.x < st) {
                float ov = sv[threadIdx.x + st]; int oi = si[threadIdx.x + st];
                if (ov < sv[threadIdx.x] ||
                    (ov == sv[threadIdx.x] && oi < si[threadIdx.x])) {
                    sv[threadIdx.x] = ov; si[threadIdx.x] = oi;
                }
            }
            __syncthreads();
        }
        if (threadIdx.x == 0) g_idx[tok] = si[0];
        __syncthreads();
    }
}

// ---------------------------------------------------------------------------
// Legacy exact argmin-GEMM (R14 pipelined; shape-guard fallback).
// ---------------------------------------------------------------------------
__global__ __launch_bounds__(256, 2) void vq_argmin_pipe(
    const float* __restrict__ x, const float* __restrict__ cb, int K)
{
    __shared__ float xs[2][BD2][BM];
    __shared__ float cs[2][BD2][2 * BK];
    const int tid = threadIdx.x;
    const int ty  = tid >> 4;
    const int tx  = tid & 15;
    const int m0  = blockIdx.x * BM;
    float best[8]; int bidx[8]; float xq[8];
    #pragma unroll
    for (int i = 0; i < 8; i++) {
        best[i] = 3.4e38f; bidx[i] = 0; xq[i] = g_xsq[m0 + ty * 8 + i];
    }
    const int lrow = tid >> 1;
    const int dg   = (tid & 1) * 8;
    const int cpt     = DIMV / BD2;
    const int ntiles  = K / BK;
    const int nchunks = ntiles * cpt;
    float4 px0, px1, pc0, pc1;
    {
        const float* xg = x + (size_t)(m0 + lrow) * DIMV + dg;
        px0 = *(const float4*)(xg);
        px1 = *(const float4*)(xg + 4);
        const float* cg = cb + (size_t)lrow * DIMV + dg;
        pc0 = *(const float4*)(cg);
        pc1 = *(const float4*)(cg + 4);
    }
    for (int t = 0; t < ntiles; t++) {
        unsigned long long acc[4][8];
        #pragma unroll
        for (int i = 0; i < 4; i++)
            #pragma unroll
            for (int j = 0; j < 8; j++) acc[i][j] = 0ULL;
        for (int dch = 0; dch < cpt; dch++) {
            const int c = t * cpt + dch;
            const int p = c & 1;
            xs[p][dg + 0][lrow] = px0.x; xs[p][dg + 1][lrow] = px0.y;
            xs[p][dg + 2][lrow] = px0.z; xs[p][dg + 3][lrow] = px0.w;
            xs[p][dg + 4][lrow] = px1.x; xs[p][dg + 5][lrow] = px1.y;
            xs[p][dg + 6][lrow] = px1.z; xs[p][dg + 7][lrow] = px1.w;
            *(float2*)&cs[p][dg + 0][2 * lrow] = make_float2(pc0.x, pc0.x);
            *(float2*)&cs[p][dg + 1][2 * lrow] = make_float2(pc0.y, pc0.y);
            *(float2*)&cs[p][dg + 2][2 * lrow] = make_float2(pc0.z, pc0.z);
            *(float2*)&cs[p][dg + 3][2 * lrow] = make_float2(pc0.w, pc0.w);
            *(float2*)&cs[p][dg + 4][2 * lrow] = make_float2(pc1.x, pc1.x);
            *(float2*)&cs[p][dg + 5][2 * lrow] = make_float2(pc1.y, pc1.y);
            *(float2*)&cs[p][dg + 6][2 * lrow] = make_float2(pc1.z, pc1.z);
            *(float2*)&cs[p][dg + 7][2 * lrow] = make_float2(pc1.w, pc1.w);
            int cn = c + 1;
            if (cn >= nchunks) cn = 0;
            const int tn = cn / cpt;
            const int dn = (cn % cpt) * BD2;
            {
                const float* xg = x + (size_t)(m0 + lrow) * DIMV + dn + dg;
                px0 = *(const float4*)(xg);
                px1 = *(const float4*)(xg + 4);
                const float* cg = cb + (size_t)(tn * BK + lrow) * DIMV + dn + dg;
                pc0 = *(const float4*)(cg);
                pc1 = *(const float4*)(cg + 4);
            }
            __syncthreads();
            #pragma unroll
            for (int dd = 0; dd < BD2; dd++) {
                unsigned long long a2[4], b2[8];
                #pragma unroll
                for (int i = 0; i < 4; i++)
                    a2[i] = *(const unsigned long long*)&xs[p][dd][ty * 8 + 2 * i];
                #pragma unroll
                for (int j = 0; j < 8; j++)
                    b2[j] = *(const unsigned long long*)&cs[p][dd][2 * (tx + 16 * j)];
                #pragma unroll
                for (int i = 0; i < 4; i++)
                    #pragma unroll
                    for (int j = 0; j < 8; j++)
                        asm("fma.rn.f32x2 %0, %1, %2, %0;"
                            : "+l"(acc[i][j]) : "l"(a2[i]), "l"(b2[j]));
            }
        }
        #pragma unroll
        for (int j = 0; j < 8; j++) {
            int code = t * BK + tx + 16 * j;
            float cq = g_csq[code];
            #pragma unroll
            for (int i2 = 0; i2 < 4; i2++) {
                unsigned long long a = acc[i2][j];
                float dlo = __uint_as_float((unsigned)(a & 0xffffffffu));
                float dhi = __uint_as_float((unsigned)(a >> 32));
                int i = 2 * i2;
                float t0 = __fmaf_rn(-2.f, dlo, xq[i]);
                float v0 = __fadd_rn(t0, cq);
                if (v0 < best[i]) { best[i] = v0; bidx[i] = code; }
                float t1 = __fmaf_rn(-2.f, dhi, xq[i + 1]);
                float v1 = __fadd_rn(t1, cq);
                if (v1 < best[i + 1]) { best[i + 1] = v1; bidx[i + 1] = code; }
            }
        }
    }
    __syncthreads();
    float* redv = &cs[0][0][0];
    int*   redi = (int*)(&cs[0][0][0] + 2048);
    #pragma unroll
    for (int i = 0; i < 8; i++) {
        int m = ty * 8 + i;
        redv[tx * 128 + m] = best[i];
        redi[tx * 128 + m] = bidx[i];
    }
    __syncthreads();
    if (tid < BM) {
        float bv = redv[tid];
        int   bi = redi[tid];
        #pragma unroll
        for (int t = 1; t < 16; t++) {
            float v  = redv[t * 128 + tid];
            int   ix = redi[t * 128 + tid];
            if (v < bv || (v == bv && ix < bi)) { bv = v; bi = ix; }
        }
        g_idx[m0 + tid] = bi;
    }
}

// ---------------------------------------------------------------------------
// Epilogue + loss (unchanged).
// ---------------------------------------------------------------------------
__global__ void epilogue_kernel(const float* __restrict__ x,
                                const float* __restrict__ cb,
                                float* __restrict__ outq,
                                float* __restrict__ outi,
                                int write_extra)
{
    __shared__ double ssum[8];
    int w = threadIdx.x >> 5, lane = threadIdx.x & 31;
    int t = blockIdx.x * 8 + w;
    int ci = g_idx[t];
    const float4* cr = (const float4*)(cb + (size_t)ci * DIMV);
    const float4* xr = (const float4*)(x + (size_t)t * DIMV);
    float4* orow = (float4*)(outq + (size_t)t * DIMV);
    double acc = 0.0;
    #pragma unroll
    for (int q = 0; q < 4; q++) {
        int f = lane + 32 * q;
        float4 c4 = cr[f];
        float4 x4 = xr[f];
        orow[f] = c4;
        double d0 = (double)c4.x - (double)x4.x;
        double d1 = (double)c4.y - (double)x4.y;
        double d2 = (double)c4.z - (double)x4.z;
        double d3 = (double)c4.w - (double)x4.w;
        acc += d0 * d0 + d1 * d1 + d2 * d2 + d3 * d3;
    }
    #pragma unroll
    for (int off = 16; off > 0; off >>= 1)
        acc += __shfl_down_sync(0xffffffffu, acc, off);
    if (lane == 0) ssum[w] = acc;
    __syncthreads();
    if (threadIdx.x == 0) {
        double s = 0.0;
        #pragma unroll
        for (int i = 0; i < 8; i++) s += ssum[i];
        g_part[blockIdx.x] = s;
    }
    if (write_extra && lane == 0) outi[t] = (float)ci;
}

__global__ void loss_kernel(int nparts, float* __restrict__ outloss, long long denom) {
    __shared__ double s[256];
    double a = 0.0;
    for (int i = threadIdx.x; i < nparts; i += 256) a += g_part[i];
    s[threadIdx.x] = a;
    __syncthreads();
    for (int st = 128; st > 0; st >>= 1) {
        if (threadIdx.x < st) s[threadIdx.x] += s[threadIdx.x + st];
        __syncthreads();
    }
    if (threadIdx.x == 0) {
        double mse = s[0] / (double)denom;
        *outloss = (float)(1.25 * mse);
    }
}

// ---------------------------------------------------------------------------
extern "C" void kernel_launch(void* const* d_in, const int* in_sizes, int n_in,
                              void* d_out, int out_size) {
    const float* x  = (const float*)d_in[0];
    const float* cb = (const float*)d_in[1];
    int n = in_sizes[0] / DIMV;
    int K = in_sizes[1] / DIMV;
    float* out = (float*)d_out;

    long long qsz = (long long)n * DIMV;
    int full = (out_size >= (int)(qsz + 1 + n)) ? 1 : 0;
    float* outloss = full ? (out + qsz) : 0;
    float* outi    = full ? (out + qsz + 1) : 0;

    csq_kernel<<<K / 8, 256>>>(cb, K);
    xsq_kernel<<<n / 8, 256>>>(x, n);

    int fast = (K % BK == 0) && (n % BM == 0) && (K <= KMAX) && (n <= NMAX);
    if (fast) {
        coarse_i8<<<n / BM, 512>>>(K);
        rescore_kernel<<<(n * 4 + 255) / 256, 256>>>(x, cb, n);
        fallback_kernel<<<256, 256>>>(x, cb, K);
    } else {
        vq_argmin_pipe<<<n / BM, 256>>>(x, cb, K);
    }

    epilogue_kernel<<<n / 8, 256>>>(x, cb, out, outi, full);
    if (full) loss_kernel<<<1, 256>>>(n / 8, outloss, qsz);
}

// round 17
// speedup vs baseline: 1.0356x; 1.0356x over previous
#include <cuda_runtime.h>
#include <cuda_fp16.h>
#include <cstdint>

#define DIMV 512
#define KMAX 8192
#define NMAX 32768

#define BM 128
#define BK 128
#define BD2 16
#define TMARGIN 5.5e-4f

// ---------------- scratch (device globals; no allocation allowed) ----------
__device__ float  g_csq[KMAX];
__device__ float  g_xsq[NMAX];
__device__ int    g_idx[NMAX];
__device__ double g_part[NMAX / 8];

__device__ __align__(16) __half2 g_xh[(size_t)NMAX * (DIMV / 2)];
__device__ __align__(16) __half2 g_ch[(size_t)KMAX * (DIMV / 2)];
__device__ int   g_ci[(size_t)NMAX * 4];
__device__ int   g_count;
__device__ int   g_list[NMAX];

// ---------------- key packing: monotone float -> uint, low 13 bits = code --
__device__ __forceinline__ uint32_t fkey(float s, int code) {
    uint32_t b = __float_as_uint(s);
    uint32_t m = (b & 0x80000000u) ? 0xFFFFFFFFu : 0x80000000u;
    return ((b ^ m) & 0xFFFFE000u) | (uint32_t)code;
}
__device__ __forceinline__ float key2f(uint32_t k) {
    uint32_t u = k & 0xFFFFE000u;
    uint32_t b = (u & 0x80000000u) ? (u ^ 0x80000000u) : ~u;
    return __uint_as_float(b);
}
__device__ __forceinline__ void ins4u(uint32_t v, uint32_t* tv) {
    if (v < tv[3]) {
        if (v < tv[2]) {
            tv[3] = tv[2];
            if (v < tv[1]) {
                tv[2] = tv[1];
                if (v < tv[0]) { tv[1] = tv[0]; tv[0] = v; }
                else           { tv[1] = v; }
            } else { tv[2] = v; }
        } else { tv[3] = v; }
    }
}
__device__ __forceinline__ __half2 u2h(uint32_t u) {
    __half2 h; *(uint32_t*)&h = u; return h;
}

// ---------------------------------------------------------------------------
// Row sum-of-squares (EXACT pipeline, op order unchanged -> feeds rescore /
// fallback bit-identically) + fp16 pack.
// ---------------------------------------------------------------------------
__global__ void xsq_kernel(const float* __restrict__ x, int rows) {
    int warp = (blockIdx.x * blockDim.x + threadIdx.x) >> 5;
    int lane = threadIdx.x & 31;
    if (warp >= rows) return;
    const float* r = x + (size_t)warp * DIMV;
    float acc = 0.f;
    #pragma unroll 4
    for (int j = lane; j < DIMV; j += 32) {
        float v = r[j];
        acc = __fadd_rn(acc, __fmul_rn(v, v));
    }
    #pragma unroll
    for (int off = 16; off > 0; off >>= 1)
        acc = __fadd_rn(acc, __shfl_down_sync(0xffffffffu, acc, off));
    if (lane == 0) g_xsq[warp] = acc;

    const float4* r4 = (const float4*)r;
    __half2* dst = g_xh + (size_t)warp * (DIMV / 2);
    #pragma unroll
    for (int q = 0; q < 4; q++) {
        float4 v = r4[lane * 4 + q];
        dst[lane * 8 + 2 * q]     = __floats2half2_rn(v.x, v.y);
        dst[lane * 8 + 2 * q + 1] = __floats2half2_rn(v.z, v.w);
    }
}

__global__ void csq_kernel(const float* __restrict__ cb, int rows) {
    if (blockIdx.x == 0 && threadIdx.x == 0) g_count = 0;
    int warp = (blockIdx.x * blockDim.x + threadIdx.x) >> 5;
    int lane = threadIdx.x & 31;
    if (warp >= rows) return;
    const float* r = cb + (size_t)warp * DIMV;
    float acc = 0.f;
    #pragma unroll 4
    for (int j = lane; j < DIMV; j += 32) {
        float v = r[j];
        acc = __fadd_rn(acc, __fmul_rn(v, v));
    }
    #pragma unroll
    for (int off = 16; off > 0; off >>= 1)
        acc = __fadd_rn(acc, __shfl_down_sync(0xffffffffu, acc, off));
    if (lane == 0) g_csq[warp] = acc;

    const float4* r4 = (const float4*)r;
    __half2* dst = g_ch + (size_t)warp * (DIMV / 2);
    #pragma unroll
    for (int q = 0; q < 4; q++) {
        float4 v = r4[lane * 4 + q];
        dst[lane * 8 + 2 * q]     = __floats2half2_rn(v.x, v.y);
        dst[lane * 8 + 2 * q + 1] = __floats2half2_rn(v.z, v.w);
    }
}

// ---------------------------------------------------------------------------
// Coarse candidate kernel: fp16 HFMA2 argmin-GEMM.
// CTA = 128 tokens, 256 threads. ty=tid>>3 owns tokens ty*4..+3; tx=tid&7
// owns codes tx*16..+15 of each 128-code tile. Double-buffered 16-dim
// chunks (8 half2 rows), register prefetch, ONE __syncthreads per chunk
// (distance-2 buffer argument identical to the validated R14 pipeline).
// Scores s = fmaf(-2, lo(acc)+hi(acc), csq) -> packed-key top-4 per token;
// 8-lane shfl merge. Token flagged if merged key3-key0 value gap < TMARGIN.
// ---------------------------------------------------------------------------
__global__ __launch_bounds__(256, 2) void coarse_h16(int K) {
    __shared__ uint32_t xs[2][8][BM];
    __shared__ uint32_t cs[2][8][BK];

    const int tid = threadIdx.x;
    const int ty  = tid >> 3;        // 0..31 -> tokens ty*4..+3
    const int tx  = tid & 7;         // 0..7  -> codes tx*16..+15
    const int m0  = blockIdx.x * BM;
    const int lrow = tid >> 1;       // staging row 0..127
    const int dg   = (tid & 1) * 4;  // half2 quad offset {0,4}

    const int tok0 = m0 + ty * 4;

    uint32_t tv[4][4];
    #pragma unroll
    for (int i = 0; i < 4; i++)
        #pragma unroll
        for (int q = 0; q < 4; q++) tv[i][q] = 0xFFFFFFFFu;

    const int ntiles = K / BK;
    const int cpt    = DIMV / BD2;         // 32 chunks per tile

    const __half2* xrow = g_xh + (size_t)(m0 + lrow) * (DIMV / 2) + dg;
    uint4 pfx = *(const uint4*)xrow;
    uint4 pfc = *(const uint4*)(g_ch + (size_t)lrow * (DIMV / 2) + dg);

    for (int t = 0; t < ntiles; t++) {
        __half2 acc[4][16];
        #pragma unroll
        for (int i = 0; i < 4; i++)
            #pragma unroll
            for (int j = 0; j < 16; j++) acc[i][j] = u2h(0u);

        for (int ch = 0; ch < cpt; ch++) {
            const int p = ch & 1;
            // commit prefetched chunk (transpose to d-pair-major)
            xs[p][dg + 0][lrow] = pfx.x;
            xs[p][dg + 1][lrow] = pfx.y;
            xs[p][dg + 2][lrow] = pfx.z;
            xs[p][dg + 3][lrow] = pfx.w;
            cs[p][dg + 0][lrow] = pfc.x;
            cs[p][dg + 1][lrow] = pfc.y;
            cs[p][dg + 2][lrow] = pfc.z;
            cs[p][dg + 3][lrow] = pfc.w;
            // prefetch next chunk (no div in hot path; wraps harmlessly)
            int chn = ch + 1;
            int tn  = t;
            if (chn == cpt) { chn = 0; tn = (t + 1 < ntiles) ? t + 1 : 0; }
            pfx = *(const uint4*)(xrow + chn * 8);
            pfc = *(const uint4*)(g_ch + (size_t)(tn * BK + lrow) * (DIMV / 2) + chn * 8 + dg);

            __syncthreads();

            #pragma unroll
            for (int dd = 0; dd < 8; dd++) {
                uint4 av = *(const uint4*)&xs[p][dd][ty * 4];
                __half2 a0 = u2h(av.x), a1 = u2h(av.y), a2 = u2h(av.z), a3 = u2h(av.w);
                #pragma unroll
                for (int jh = 0; jh < 4; jh++) {
                    uint4 bv = *(const uint4*)&cs[p][dd][tx * 16 + jh * 4];
                    const uint32_t* br = &bv.x;
                    #pragma unroll
                    for (int jj = 0; jj < 4; jj++) {
                        __half2 b = u2h(br[jj]);
                        int j = jh * 4 + jj;
                        acc[0][j] = __hfma2(a0, b, acc[0][j]);
                        acc[1][j] = __hfma2(a1, b, acc[1][j]);
                        acc[2][j] = __hfma2(a2, b, acc[2][j]);
                        acc[3][j] = __hfma2(a3, b, acc[3][j]);
                    }
                }
            }
        }

        // finalize tile: s = fmaf(-2, lo+hi, csq); packed-key top-4
        #pragma unroll
        for (int j = 0; j < 16; j++) {
            int code = t * BK + tx * 16 + j;
            float cq = __ldg(&g_csq[code]);
            #pragma unroll
            for (int i = 0; i < 4; i++) {
                float d = __low2float(acc[i][j]) + __high2float(acc[i][j]);
                float s = __fmaf_rn(-2.f, d, cq);
                ins4u(fkey(s, code), tv[i]);
            }
        }
    }

    // merge the 8 tx-lanes per token group (xor 1,2,4 stays within octet)
    #pragma unroll
    for (int off = 1; off <= 4; off <<= 1) {
        #pragma unroll
        for (int i = 0; i < 4; i++) {
            uint32_t ov[4];
            #pragma unroll
            for (int q = 0; q < 4; q++)
                ov[q] = __shfl_xor_sync(0xffffffffu, tv[i][q], off);
            #pragma unroll
            for (int q = 0; q < 4; q++) ins4u(ov[q], tv[i]);
        }
    }

    if (tx == 0) {
        #pragma unroll
        for (int i = 0; i < 4; i++) {
            int tok = tok0 + i;
            #pragma unroll
            for (int q = 0; q < 4; q++)
                g_ci[4 * tok + q] = (int)(tv[i][q] & 0x1FFFu);
            if (key2f(tv[i][3]) - key2f(tv[i][0]) < TMARGIN) {
                int p = atomicAdd(&g_count, 1);
                g_list[p] = tok;
            }
        }
    }
}

// ---------------------------------------------------------------------------
// Exact rescore of the 4 candidates: bit-identical R4 pipeline.
// ---------------------------------------------------------------------------
__global__ void rescore_kernel(const float* __restrict__ x,
                               const float* __restrict__ cb, int n) {
    int gt = blockIdx.x * blockDim.x + threadIdx.x;
    int tok = gt >> 2, j = gt & 3;
    if (tok >= n) return;
    int code = g_ci[4 * tok + j];
    const float4* xr = (const float4*)(x + (size_t)tok * DIMV);
    const float4* cr = (const float4*)(cb + (size_t)code * DIMV);
    float acc = 0.f;
    #pragma unroll 8
    for (int q = 0; q < DIMV / 4; q++) {
        float4 a = __ldg(xr + q), c = __ldg(cr + q);
        acc = __fmaf_rn(a.x, c.x, acc);
        acc = __fmaf_rn(a.y, c.y, acc);
        acc = __fmaf_rn(a.z, c.z, acc);
        acc = __fmaf_rn(a.w, c.w, acc);
    }
    float v = __fadd_rn(__fmaf_rn(-2.f, acc, g_xsq[tok]), g_csq[code]);
    #pragma unroll
    for (int off = 1; off < 4; off <<= 1) {
        float ov = __shfl_xor_sync(0xffffffffu, v, off);
        int   oc = __shfl_xor_sync(0xffffffffu, code, off);
        if (ov < v || (ov == v && oc < code)) { v = ov; code = oc; }
    }
    if (j == 0) g_idx[tok] = code;
}

// ---------------------------------------------------------------------------
// Fallback: full exact scan for flagged tokens (few %).
// ---------------------------------------------------------------------------
__global__ void fallback_kernel(const float* __restrict__ x,
                                const float* __restrict__ cb, int K) {
    __shared__ float sv[256];
    __shared__ int   si[256];
    int nf = g_count;
    for (int li = blockIdx.x; li < nf; li += gridDim.x) {
        int tok = g_list[li];
        float xsq = g_xsq[tok];
        const float4* xr = (const float4*)(x + (size_t)tok * DIMV);
        float bv = 3.4e38f; int bi = 0x7fffffff;
        for (int code = threadIdx.x; code < K; code += 256) {
            const float4* cr = (const float4*)(cb + (size_t)code * DIMV);
            float acc = 0.f;
            #pragma unroll 8
            for (int q = 0; q < DIMV / 4; q++) {
                float4 a = xr[q], c = __ldg(cr + q);
                acc = __fmaf_rn(a.x, c.x, acc);
                acc = __fmaf_rn(a.y, c.y, acc);
                acc = __fmaf_rn(a.z, c.z, acc);
                acc = __fmaf_rn(a.w, c.w, acc);
            }
            float v = __fadd_rn(__fmaf_rn(-2.f, acc, xsq), g_csq[code]);
            if (v < bv || (v == bv && code < bi)) { bv = v; bi = code; }
        }
        sv[threadIdx.x] = bv; si[threadIdx.x] = bi;
        __syncthreads();
        for (int st = 128; st > 0; st >>= 1) {
            if (threadIdx.x < st) {
                float ov = sv[threadIdx.x + st]; int oi = si[threadIdx.x + st];
                if (ov < sv[threadIdx.x] ||
                    (ov == sv[threadIdx.x] && oi < si[threadIdx.x])) {
                    sv[threadIdx.x] = ov; si[threadIdx.x] = oi;
                }
            }
            __syncthreads();
        }
        if (threadIdx.x == 0) g_idx[tok] = si[0];
        __syncthreads();
    }
}

// ---------------------------------------------------------------------------
// Legacy exact argmin-GEMM (R14 pipelined; shape-guard fallback).
// ---------------------------------------------------------------------------
__global__ __launch_bounds__(256, 2) void vq_argmin_pipe(
    const float* __restrict__ x, const float* __restrict__ cb, int K)
{
    __shared__ float xs[2][BD2][BM];
    __shared__ float cs[2][BD2][2 * BK];
    const int tid = threadIdx.x;
    const int ty  = tid >> 4;
    const int tx  = tid & 15;
    const int m0  = blockIdx.x * BM;
    float best[8]; int bidx[8]; float xq[8];
    #pragma unroll
    for (int i = 0; i < 8; i++) {
        best[i] = 3.4e38f; bidx[i] = 0; xq[i] = g_xsq[m0 + ty * 8 + i];
    }
    const int lrow = tid >> 1;
    const int dg   = (tid & 1) * 8;
    const int cpt     = DIMV / BD2;
    const int ntiles  = K / BK;
    const int nchunks = ntiles * cpt;
    float4 px0, px1, pc0, pc1;
    {
        const float* xg = x + (size_t)(m0 + lrow) * DIMV + dg;
        px0 = *(const float4*)(xg);
        px1 = *(const float4*)(xg + 4);
        const float* cg = cb + (size_t)lrow * DIMV + dg;
        pc0 = *(const float4*)(cg);
        pc1 = *(const float4*)(cg + 4);
    }
    for (int t = 0; t < ntiles; t++) {
        unsigned long long acc[4][8];
        #pragma unroll
        for (int i = 0; i < 4; i++)
            #pragma unroll
            for (int j = 0; j < 8; j++) acc[i][j] = 0ULL;
        for (int dch = 0; dch < cpt; dch++) {
            const int c = t * cpt + dch;
            const int p = c & 1;
            xs[p][dg + 0][lrow] = px0.x; xs[p][dg + 1][lrow] = px0.y;
            xs[p][dg + 2][lrow] = px0.z; xs[p][dg + 3][lrow] = px0.w;
            xs[p][dg + 4][lrow] = px1.x; xs[p][dg + 5][lrow] = px1.y;
            xs[p][dg + 6][lrow] = px1.z; xs[p][dg + 7][lrow] = px1.w;
            *(float2*)&cs[p][dg + 0][2 * lrow] = make_float2(pc0.x, pc0.x);
            *(float2*)&cs[p][dg + 1][2 * lrow] = make_float2(pc0.y, pc0.y);
            *(float2*)&cs[p][dg + 2][2 * lrow] = make_float2(pc0.z, pc0.z);
            *(float2*)&cs[p][dg + 3][2 * lrow] = make_float2(pc0.w, pc0.w);
            *(float2*)&cs[p][dg + 4][2 * lrow] = make_float2(pc1.x, pc1.x);
            *(float2*)&cs[p][dg + 5][2 * lrow] = make_float2(pc1.y, pc1.y);
            *(float2*)&cs[p][dg + 6][2 * lrow] = make_float2(pc1.z, pc1.z);
            *(float2*)&cs[p][dg + 7][2 * lrow] = make_float2(pc1.w, pc1.w);
            int cn = c + 1;
            if (cn >= nchunks) cn = 0;
            const int tn = cn / cpt;
            const int dn = (cn % cpt) * BD2;
            {
                const float* xg = x + (size_t)(m0 + lrow) * DIMV + dn + dg;
                px0 = *(const float4*)(xg);
                px1 = *(const float4*)(xg + 4);
                const float* cg = cb + (size_t)(tn * BK + lrow) * DIMV + dn + dg;
                pc0 = *(const float4*)(cg);
                pc1 = *(const float4*)(cg + 4);
            }
            __syncthreads();
            #pragma unroll
            for (int dd = 0; dd < BD2; dd++) {
                unsigned long long a2[4], b2[8];
                #pragma unroll
                for (int i = 0; i < 4; i++)
                    a2[i] = *(const unsigned long long*)&xs[p][dd][ty * 8 + 2 * i];
                #pragma unroll
                for (int j = 0; j < 8; j++)
                    b2[j] = *(const unsigned long long*)&cs[p][dd][2 * (tx + 16 * j)];
                #pragma unroll
                for (int i = 0; i < 4; i++)
                    #pragma unroll
                    for (int j = 0; j < 8; j++)
                        asm("fma.rn.f32x2 %0, %1, %2, %0;"
                            : "+l"(acc[i][j]) : "l"(a2[i]), "l"(b2[j]));
            }
        }
        #pragma unroll
        for (int j = 0; j < 8; j++) {
            int code = t * BK + tx + 16 * j;
            float cq = g_csq[code];
            #pragma unroll
            for (int i2 = 0; i2 < 4; i2++) {
                unsigned long long a = acc[i2][j];
                float dlo = __uint_as_float((unsigned)(a & 0xffffffffu));
                float dhi = __uint_as_float((unsigned)(a >> 32));
                int i = 2 * i2;
                float t0 = __fmaf_rn(-2.f, dlo, xq[i]);
                float v0 = __fadd_rn(t0, cq);
                if (v0 < best[i]) { best[i] = v0; bidx[i] = code; }
                float t1 = __fmaf_rn(-2.f, dhi, xq[i + 1]);
                float v1 = __fadd_rn(t1, cq);
                if (v1 < best[i + 1]) { best[i + 1] = v1; bidx[i + 1] = code; }
            }
        }
    }
    __syncthreads();
    float* redv = &cs[0][0][0];
    int*   redi = (int*)(&cs[0][0][0] + 2048);
    #pragma unroll
    for (int i = 0; i < 8; i++) {
        int m = ty * 8 + i;
        redv[tx * 128 + m] = best[i];
        redi[tx * 128 + m] = bidx[i];
    }
    __syncthreads();
    if (tid < BM) {
        float bv = redv[tid];
        int   bi = redi[tid];
        #pragma unroll
        for (int t = 1; t < 16; t++) {
            float v  = redv[t * 128 + tid];
            int   ix = redi[t * 128 + tid];
            if (v < bv || (v == bv && ix < bi)) { bv = v; bi = ix; }
        }
        g_idx[m0 + tid] = bi;
    }
}

// ---------------------------------------------------------------------------
// Epilogue + loss (unchanged).
// ---------------------------------------------------------------------------
__global__ void epilogue_kernel(const float* __restrict__ x,
                                const float* __restrict__ cb,
                                float* __restrict__ outq,
                                float* __restrict__ outi,
                                int write_extra)
{
    __shared__ double ssum[8];
    int w = threadIdx.x >> 5, lane = threadIdx.x & 31;
    int t = blockIdx.x * 8 + w;
    int ci = g_idx[t];
    const float4* cr = (const float4*)(cb + (size_t)ci * DIMV);
    const float4* xr = (const float4*)(x + (size_t)t * DIMV);
    float4* orow = (float4*)(outq + (size_t)t * DIMV);
    double acc = 0.0;
    #pragma unroll
    for (int q = 0; q < 4; q++) {
        int f = lane + 32 * q;
        float4 c4 = cr[f];
        float4 x4 = xr[f];
        orow[f] = c4;
        double d0 = (double)c4.x - (double)x4.x;
        double d1 = (double)c4.y - (double)x4.y;
        double d2 = (double)c4.z - (double)x4.z;
        double d3 = (double)c4.w - (double)x4.w;
        acc += d0 * d0 + d1 * d1 + d2 * d2 + d3 * d3;
    }
    #pragma unroll
    for (int off = 16; off > 0; off >>= 1)
        acc += __shfl_down_sync(0xffffffffu, acc, off);
    if (lane == 0) ssum[w] = acc;
    __syncthreads();
    if (threadIdx.x == 0) {
        double s = 0.0;
        #pragma unroll
        for (int i = 0; i < 8; i++) s += ssum[i];
        g_part[blockIdx.x] = s;
    }
    if (write_extra && lane == 0) outi[t] = (float)ci;
}

__global__ void loss_kernel(int nparts, float* __restrict__ outloss, long long denom) {
    __shared__ double s[256];
    double a = 0.0;
    for (int i = threadIdx.x; i < nparts; i += 256) a += g_part[i];
    s[threadIdx.x] = a;
    __syncthreads();
    for (int st = 128; st > 0; st >>= 1) {
        if (threadIdx.x < st) s[threadIdx.x] += s[threadIdx.x + st];
        __syncthreads();
    }
    if (threadIdx.x == 0) {
        double mse = s[0] / (double)denom;
        *outloss = (float)(1.25 * mse);
    }
}

// ---------------------------------------------------------------------------
extern "C" void kernel_launch(void* const* d_in, const int* in_sizes, int n_in,
                              void* d_out, int out_size) {
    const float* x  = (const float*)d_in[0];
    const float* cb = (const float*)d_in[1];
    int n = in_sizes[0] / DIMV;
    int K = in_sizes[1] / DIMV;
    float* out = (float*)d_out;

    long long qsz = (long long)n * DIMV;
    int full = (out_size >= (int)(qsz + 1 + n)) ? 1 : 0;
    float* outloss = full ? (out + qsz) : 0;
    float* outi    = full ? (out + qsz + 1) : 0;

    csq_kernel<<<K / 8, 256>>>(cb, K);
    xsq_kernel<<<n / 8, 256>>>(x, n);

    int fast = (K % BK == 0) && (n % BM == 0) && (K <= KMAX) && (n <= NMAX);
    if (fast) {
        coarse_h16<<<n / BM, 256>>>(K);
        rescore_kernel<<<(n * 4 + 255) / 256, 256>>>(x, cb, n);
        fallback_kernel<<<256, 256>>>(x, cb, K);
    } else {
        vq_argmin_pipe<<<n / BM, 256>>>(x, cb, K);
    }

    epilogue_kernel<<<n / 8, 256>>>(x, cb, out, outi, full);
    if (full) loss_kernel<<<1, 256>>>(n / 8, outloss, qsz);
}